// round 7
// baseline (speedup 1.0000x reference)
#include <cuda_runtime.h>
#include <cuda_bf16.h>

// Problem constants
#define H   1024
#define B   64
#define S   512
#define W3H 3072            // W row stride (3*H)
#define BLKS_PER_B 16       // fused kernel: 16 blocks per batch row, 32 rows each
#define ROWS_PER_WARP 4

// Scratch (zero-initialized at module load; every launch self-cleans, so each
// graph replay is deterministic).
__device__ float g_u2[H];            // u2 = W[:, 2H:3H]^T v   (accumulated, then reset)
__device__ float g_scores[B * S];    // pre-softmax scores
__device__ int   g_cnt[B];           // per-b completion counters (reset by per-b last)
__device__ int   g_gcnt;             // global completion counter (reset by global last)

// ---------------------------------------------------------------------------
// Kernel 1: u2[k] += sum_h v[h] * W[h, 2H + k]       (g_u2 pre-zeroed)
// grid = (4, 32): x tiles k, y tiles h. atomicAdd partials (distinct addrs).
// ---------------------------------------------------------------------------
__global__ void k_u2(const float* __restrict__ W, const float* __restrict__ v) {
    const int tx = threadIdx.x & 63;   // k-float4 lane within block tile
    const int ty = threadIdx.x >> 6;   // h slice (0..3)
    const int k4 = blockIdx.x * 64 + tx;
    const int h0 = blockIdx.y * 32 + ty;

    float4 acc = make_float4(0.f, 0.f, 0.f, 0.f);
#pragma unroll
    for (int j = 0; j < 8; j++) {
        const int h = h0 + j * 4;
        const float vh = __ldg(&v[h]);
        const float4 w = __ldg((const float4*)(W + (size_t)h * W3H + 2 * H) + k4);
        acc.x += vh * w.x;
        acc.y += vh * w.y;
        acc.z += vh * w.z;
        acc.w += vh * w.w;
    }

    __shared__ float4 sm[4][64];
    sm[ty][tx] = acc;
    __syncthreads();
    if (ty == 0) {
        float4 s = sm[0][tx];
#pragma unroll
        for (int j = 1; j < 4; j++) {
            const float4 p = sm[j][tx];
            s.x += p.x; s.y += p.y; s.z += p.z; s.w += p.w;
        }
        float* dst = g_u2 + k4 * 4;
        atomicAdd(dst + 0, s.x);
        atomicAdd(dst + 1, s.y);
        atomicAdd(dst + 2, s.z);
        atomicAdd(dst + 3, s.w);
    }
}

// ---------------------------------------------------------------------------
// Kernel 2 (fused): scores + per-b softmax + self-clean.
// SINGLE-WAVE grid: 1024 blocks x 256 threads (<= 148 SMs x 8 co-resident),
// all blocks resident at once -> no wave-tail quantization (R6 lost ~4.7us
// to a 46%-full 4th wave). Each warp streams 4 consecutive rows.
// ---------------------------------------------------------------------------
__global__ void __launch_bounds__(256, 8)
k_fused(const float4* __restrict__ enc, float* __restrict__ out) {
    const int b     = blockIdx.x >> 4;            // 16 blocks per b
    const int chunk = blockIdx.x & 15;
    const int warp  = threadIdx.x >> 5;
    const int lane  = threadIdx.x & 31;
    const int tid   = threadIdx.x;
    const int row0  = b * S + chunk * 32 + warp * ROWS_PER_WARP;

    const float4* __restrict__ u = (const float4*)g_u2;

    for (int rr = 0; rr < ROWS_PER_WARP; rr++) {
        const int row = row0 + rr;
        const float4* __restrict__ rp = enc + (size_t)row * (H / 4);

        float acc = 0.f;
#pragma unroll
        for (int j = 0; j < 8; j++) {
            const float4 e = __ldg(&rp[lane + j * 32]);
            const float4 w = __ldg(&u[lane + j * 32]);   // L1-hot after first touch
            acc += e.x * w.x + e.y * w.y + e.z * w.z + e.w * w.w;
        }
#pragma unroll
        for (int off = 16; off > 0; off >>= 1)
            acc += __shfl_xor_sync(0xffffffffu, acc, off);
        if (lane == 0) g_scores[row] = acc;
    }

    // --- single-thread release + ticket ---
    __shared__ int s_ticket;
    __syncthreads();                     // block's score STGs CTA-visible
    if (tid == 0) {
        __threadfence();                 // cumulative release to gpu scope
        s_ticket = atomicAdd(&g_cnt[b], 1);
        if (s_ticket == BLKS_PER_B - 1)
            __threadfence();             // acquire for the re-reads below
    }
    __syncthreads();

    if (s_ticket == BLKS_PER_B - 1) {
        const float* sc = g_scores + b * S;
        const float v0 = __ldcg(&sc[tid]);
        const float v1 = __ldcg(&sc[tid + 256]);

        __shared__ float sm[256];
        sm[tid] = fmaxf(v0, v1);
        __syncthreads();
#pragma unroll
        for (int st = 128; st > 0; st >>= 1) {
            if (tid < st) sm[tid] = fmaxf(sm[tid], sm[tid + st]);
            __syncthreads();
        }
        const float mx = sm[0];
        __syncthreads();

        const float e0 = __expf(v0 - mx);
        const float e1 = __expf(v1 - mx);
        sm[tid] = e0 + e1;
        __syncthreads();
#pragma unroll
        for (int st = 128; st > 0; st >>= 1) {
            if (tid < st) sm[tid] += sm[tid + st];
            __syncthreads();
        }
        const float inv = 1.f / sm[0];

        out[b * S + tid]       = e0 * inv;
        out[b * S + tid + 256] = e1 * inv;

        // --- self-clean for the next launch ---
        if (tid == 0) {
            g_cnt[b] = 0;
            __threadfence();
            const int g = atomicAdd(&g_gcnt, 1);
            s_ticket = (g == B - 1) ? 1 : 0;
        }
        __syncthreads();
        if (s_ticket == 1) {
            // globally last block: all per-b softmaxes done => u2 fully consumed
            ((float4*)g_u2)[tid] = make_float4(0.f, 0.f, 0.f, 0.f);
            if (tid == 0) g_gcnt = 0;
        }
    }
}

// ---------------------------------------------------------------------------
// Inputs (metadata order): hidden[2,B,H], encoder_outputs[B,S,H],
//                          W[H,3H], b[H], v[H]
// hidden and b are mathematically irrelevant post-softmax (per-row constants).
// ---------------------------------------------------------------------------
extern "C" void kernel_launch(void* const* d_in, const int* in_sizes, int n_in,
                              void* d_out, int out_size) {
    const float* enc = (const float*)d_in[1];
    const float* W   = (const float*)d_in[2];
    const float* v   = (const float*)d_in[4];
    float* out = (float*)d_out;

    {
        dim3 grid(4, 32);
        k_u2<<<grid, 256>>>(W, v);
    }
    k_fused<<<B * BLKS_PER_B, 256>>>((const float4*)enc, out);
}

// round 8
// speedup vs baseline: 1.1231x; 1.1231x over previous
#include <cuda_runtime.h>
#include <cuda_bf16.h>
#include <cstdint>

// Problem constants
#define H   1024
#define B   64
#define S   512
#define W3H 3072            // W row stride (3*H)
#define BLKS_PER_B 8        // 8 blocks per batch entry
#define ROWS_PER_BLK 64     // rows per block
#define CHUNK_ROWS 4        // rows per TMA chunk
#define NCHUNK (ROWS_PER_BLK / CHUNK_ROWS)       // 16
#define CHUNK_BYTES (CHUNK_ROWS * H * 4)         // 16384

// Scratch (zero-initialized at module load; every launch self-cleans, so each
// graph replay is deterministic).
__device__ float g_u2[H];
__device__ float g_scores[B * S];
__device__ int   g_cnt[B];
__device__ int   g_gcnt;

// ---------------------------------------------------------------------------
// mbarrier / bulk-copy PTX helpers
// ---------------------------------------------------------------------------
__device__ __forceinline__ uint32_t smem_u32(const void* p) {
    return (uint32_t)__cvta_generic_to_shared(p);
}
__device__ __forceinline__ void mbar_init(uint32_t a, uint32_t cnt) {
    asm volatile("mbarrier.init.shared.b64 [%0], %1;" :: "r"(a), "r"(cnt) : "memory");
}
__device__ __forceinline__ void mbar_expect(uint32_t a, uint32_t bytes) {
    asm volatile("mbarrier.arrive.expect_tx.shared.b64 _, [%0], %1;"
                 :: "r"(a), "r"(bytes) : "memory");
}
__device__ __forceinline__ void bulk_g2s(uint32_t dst, const void* src,
                                         uint32_t bytes, uint32_t mbar) {
    asm volatile("cp.async.bulk.shared::cta.global.mbarrier::complete_tx::bytes "
                 "[%0], [%1], %2, [%3];"
                 :: "r"(dst), "l"(src), "r"(bytes), "r"(mbar) : "memory");
}
__device__ __forceinline__ void mbar_wait(uint32_t a, uint32_t parity) {
    uint32_t done;
    do {
        asm volatile("{\n\t.reg .pred p;\n\t"
                     "mbarrier.try_wait.parity.shared.b64 p, [%1], %2, 0x989680;\n\t"
                     "selp.b32 %0, 1, 0, p;\n\t}"
                     : "=r"(done) : "r"(a), "r"(parity) : "memory");
    } while (!done);
}
__device__ __forceinline__ void fence_async_smem() {
    asm volatile("fence.proxy.async.shared::cta;" ::: "memory");
}

// ---------------------------------------------------------------------------
// Kernel 1: u2[k] += sum_h v[h] * W[h, 2H + k]       (g_u2 pre-zeroed)
// ---------------------------------------------------------------------------
__global__ void k_u2(const float* __restrict__ W, const float* __restrict__ v) {
    const int tx = threadIdx.x & 63;
    const int ty = threadIdx.x >> 6;
    const int k4 = blockIdx.x * 64 + tx;
    const int h0 = blockIdx.y * 32 + ty;

    float4 acc = make_float4(0.f, 0.f, 0.f, 0.f);
#pragma unroll
    for (int j = 0; j < 8; j++) {
        const int h = h0 + j * 4;
        const float vh = __ldg(&v[h]);
        const float4 w = __ldg((const float4*)(W + (size_t)h * W3H + 2 * H) + k4);
        acc.x += vh * w.x; acc.y += vh * w.y; acc.z += vh * w.z; acc.w += vh * w.w;
    }

    __shared__ float4 sm[4][64];
    sm[ty][tx] = acc;
    __syncthreads();
    if (ty == 0) {
        float4 s = sm[0][tx];
#pragma unroll
        for (int j = 1; j < 4; j++) {
            const float4 p = sm[j][tx];
            s.x += p.x; s.y += p.y; s.z += p.z; s.w += p.w;
        }
        float* dst = g_u2 + k4 * 4;
        atomicAdd(dst + 0, s.x);
        atomicAdd(dst + 1, s.y);
        atomicAdd(dst + 2, s.z);
        atomicAdd(dst + 3, s.w);
    }
}

// ---------------------------------------------------------------------------
// Kernel 2: TMA-streamed scores + per-b softmax + self-clean.
// 512 blocks x 256 threads, 64 rows/block, 16 chunks of 4 rows (16KB) each,
// double-buffered cp.async.bulk -> smem, compute from smem (no LDG hot path).
// ---------------------------------------------------------------------------
__global__ void __launch_bounds__(256)
k_fused(const float* __restrict__ enc, float* __restrict__ out) {
    __shared__ alignas(128) float s_buf[2][CHUNK_ROWS][H];   // 32 KB
    __shared__ alignas(16)  float s_u2[H];                    // 4 KB
    __shared__ float s_part[CHUNK_ROWS][2];
    __shared__ alignas(8) unsigned long long s_mbar[2];
    __shared__ int s_ticket;
    __shared__ float s_sm[256];

    const int tid  = threadIdx.x;
    const int warp = tid >> 5;
    const int lane = tid & 31;
    const int b    = blockIdx.x >> 3;
    const int row0 = blockIdx.x * ROWS_PER_BLK;   // global row base

    // stage u2 into smem (fresh via L2)
    ((float4*)s_u2)[tid] = __ldcg(((const float4*)g_u2) + tid);

    const uint32_t mb0 = smem_u32(&s_mbar[0]);
    const uint32_t mb1 = smem_u32(&s_mbar[1]);
    const uint32_t sb0 = smem_u32(&s_buf[0][0][0]);
    const uint32_t sb1 = smem_u32(&s_buf[1][0][0]);

    if (tid == 0) {
        mbar_init(mb0, 1);
        mbar_init(mb1, 1);
        fence_async_smem();
        // prologue: issue chunks 0 and 1
        mbar_expect(mb0, CHUNK_BYTES);
        bulk_g2s(sb0, enc + (size_t)row0 * H, CHUNK_BYTES, mb0);
        mbar_expect(mb1, CHUNK_BYTES);
        bulk_g2s(sb1, enc + (size_t)(row0 + CHUNK_ROWS) * H, CHUNK_BYTES, mb1);
    }
    __syncthreads();

    const int r    = warp >> 1;        // row within chunk (0..3)
    const int half = warp & 1;         // which half of the row
    const int base = half * 512 + lane * 4;   // float index into row

    for (int c = 0; c < NCHUNK; c++) {
        const uint32_t mb = (c & 1) ? mb1 : mb0;
        mbar_wait(mb, (c >> 1) & 1);

        // compute: 2 warps per row, 4 float4 per lane from smem
        const float* rowp = &s_buf[c & 1][r][0];
        float acc = 0.f;
#pragma unroll
        for (int k = 0; k < 4; k++) {
            const float4 e = *(const float4*)(rowp + base + k * 128);
            const float4 w = *(const float4*)(s_u2 + base + k * 128);
            acc += e.x * w.x + e.y * w.y + e.z * w.z + e.w * w.w;
        }
#pragma unroll
        for (int off = 16; off > 0; off >>= 1)
            acc += __shfl_xor_sync(0xffffffffu, acc, off);
        if (lane == 0) s_part[r][half] = acc;
        __syncthreads();                      // buffer reads + partials done

        if (tid < CHUNK_ROWS)
            g_scores[row0 + c * CHUNK_ROWS + tid] = s_part[tid][0] + s_part[tid][1];

        if (tid == 0 && c + 2 < NCHUNK) {
            fence_async_smem();               // order smem reads before async reuse
            mbar_expect(mb, CHUNK_BYTES);
            bulk_g2s((c & 1) ? sb1 : sb0,
                     enc + (size_t)(row0 + (c + 2) * CHUNK_ROWS) * H,
                     CHUNK_BYTES, mb);
        }
    }

    // --- single-thread release + ticket ---
    __syncthreads();
    if (tid == 0) {
        __threadfence();
        s_ticket = atomicAdd(&g_cnt[b], 1);
        if (s_ticket == BLKS_PER_B - 1)
            __threadfence();                  // acquire for re-reads
    }
    __syncthreads();

    if (s_ticket == BLKS_PER_B - 1) {
        const float* sc = g_scores + b * S;
        const float v0 = __ldcg(&sc[tid]);
        const float v1 = __ldcg(&sc[tid + 256]);

        s_sm[tid] = fmaxf(v0, v1);
        __syncthreads();
#pragma unroll
        for (int st = 128; st > 0; st >>= 1) {
            if (tid < st) s_sm[tid] = fmaxf(s_sm[tid], s_sm[tid + st]);
            __syncthreads();
        }
        const float mx = s_sm[0];
        __syncthreads();

        const float e0 = __expf(v0 - mx);
        const float e1 = __expf(v1 - mx);
        s_sm[tid] = e0 + e1;
        __syncthreads();
#pragma unroll
        for (int st = 128; st > 0; st >>= 1) {
            if (tid < st) s_sm[tid] += s_sm[tid + st];
            __syncthreads();
        }
        const float inv = 1.f / s_sm[0];

        out[b * S + tid]       = e0 * inv;
        out[b * S + tid + 256] = e1 * inv;

        // --- self-clean for the next launch ---
        if (tid == 0) {
            g_cnt[b] = 0;
            __threadfence();
            const int g = atomicAdd(&g_gcnt, 1);
            s_ticket = (g == B - 1) ? 1 : 0;
        }
        __syncthreads();
        if (s_ticket == 1) {
            ((float4*)g_u2)[tid] = make_float4(0.f, 0.f, 0.f, 0.f);
            if (tid == 0) g_gcnt = 0;
        }
    }
}

// ---------------------------------------------------------------------------
// Inputs (metadata order): hidden[2,B,H], encoder_outputs[B,S,H],
//                          W[H,3H], b[H], v[H]
// hidden and b are mathematically irrelevant post-softmax (per-row constants).
// ---------------------------------------------------------------------------
extern "C" void kernel_launch(void* const* d_in, const int* in_sizes, int n_in,
                              void* d_out, int out_size) {
    const float* enc = (const float*)d_in[1];
    const float* W   = (const float*)d_in[2];
    const float* v   = (const float*)d_in[4];
    float* out = (float*)d_out;

    {
        dim3 grid(4, 32);
        k_u2<<<grid, 256>>>(W, v);
    }
    k_fused<<<B * BLKS_PER_B, 256>>>(enc, out);
}